// round 11
// baseline (speedup 1.0000x reference)
#include <cuda_runtime.h>
#include <cuda_bf16.h>
#include <math.h>

#define BB 32
#define EMB 512
#define DH 1024
#define LL 64
#define VV 32000
#define G4 4096
#define NPO 125          // outproj n-blocks (256 cols each)

// ---------------- bf16 uint4 fragment weights: [nt][ktp][lane], 2 kt per uint4 ----------------
__device__ uint4 Bout4[(size_t)4000 * 32 * 32];
__device__ uint4 Bdec4[(size_t)512 * 64 * 32];   // gate-permuted cols
__device__ uint4 Benc4[(size_t)512 * 48 * 32];   // gate-permuted cols
__device__ uint4 Bcomb4[(size_t)128 * 64 * 32];
__device__ float g_attnT[LL * 2 * DH];

// ---------------- state / partials ----------------
__device__ float g_h[BB * DH];
__device__ float g_c[BB * DH];
__device__ float g_inp[BB * DH];
__device__ float g_ctx[BB * DH];
__device__ float g_eo2[BB * LL * DH];
__device__ float g_gp[16 * BB * G4];
__device__ float g_cpp[16 * BB * DH];
__device__ float g_lg[2 * BB * VV];
__device__ float g_psum[BB * NPO];
__device__ float g_pmax[BB * NPO];
__device__ int   g_pidx[BB * NPO];
__device__ int   g_tok[BB];
__device__ float g_lse[LL * BB];
__device__ int g_cnt_enc[LL * 16];
__device__ int g_cnt_dec[LL * 16];
__device__ int g_cnt_comb[LL * 4];
__device__ int g_cnt_out[LL * NPO];

// ---------------- helpers ----------------
__device__ __forceinline__ unsigned packbf(float x, float y) {
    unsigned lo = __bfloat16_as_ushort(__float2bfloat16_rn(x));
    unsigned hi = __bfloat16_as_ushort(__float2bfloat16_rn(y));
    return lo | (hi << 16);
}
__device__ __forceinline__ void mma16816(float* c, uint4 a, uint2 b) {
    asm volatile(
        "mma.sync.aligned.m16n8k16.row.col.f32.bf16.bf16.f32 "
        "{%0,%1,%2,%3}, {%4,%5,%6,%7}, {%8,%9}, {%0,%1,%2,%3};"
        : "+f"(c[0]), "+f"(c[1]), "+f"(c[2]), "+f"(c[3])
        : "r"(a.x), "r"(a.y), "r"(a.z), "r"(a.w), "r"(b.x), "r"(b.y));
}
__device__ __forceinline__ float sigm(float x) { return 1.f / (1.f + expf(-x)); }
__device__ __forceinline__ unsigned sptr(const void* p) {
    return (unsigned)__cvta_generic_to_shared(p);
}
__device__ __forceinline__ void cpa16(unsigned s, const void* g) {
    asm volatile("cp.async.cg.shared.global [%0], [%1], 16;" :: "r"(s), "l"(g));
}
#define CP_COMMIT() asm volatile("cp.async.commit_group;")
#define CP_WAIT0()  asm volatile("cp.async.wait_group 0;")
#define CP_WAIT1()  asm volatile("cp.async.wait_group 1;")

// ---------------- init ----------------
__global__ void k_init(int phase) {
    int i = blockIdx.x * blockDim.x + threadIdx.x;
    if (i < BB * DH) { g_h[i] = 0.f; g_c[i] = 0.f; }
    if (phase == 0) {
        if (i < LL * 16) { g_cnt_enc[i] = 0; g_cnt_dec[i] = 0; }
        if (i < LL * 4)  g_cnt_comb[i] = 0;
        if (i < LL * NPO) g_cnt_out[i] = 0;
    } else {
        if (i < BB) g_tok[i] = 127;
    }
}

// ---------------- B prep: W[k][n] f32 -> [nt][ktp][lane] uint4 (2 kt) ----------------
__global__ void k_prepB4(const float* __restrict__ W0, const float* __restrict__ W1,
                         int kbnd, int N, int KTPT, int NT, int perm,
                         uint4* __restrict__ dst) {
    size_t idx = (size_t)blockIdx.x * blockDim.x + threadIdx.x;
    size_t total = (size_t)NT * KTPT * 32;
    if (idx >= total) return;
    int lane = (int)(idx & 31);
    int ktp = (int)((idx >> 5) % KTPT);
    int nt = (int)(idx / ((size_t)KTPT * 32));
    int g = lane >> 2, tg = lane & 3;
    int n = nt * 8 + g;
    if (perm) {
        int p = n >> 7, r = n & 127, gate = r >> 5, u = r & 31;
        n = gate * DH + (p << 5) + u;
    }
    unsigned rr[4];
#pragma unroll
    for (int h = 0; h < 2; h++) {
        int kt = 2 * ktp + h;
        int kb = kt * 16 + tg * 2;
        float w[4];
#pragma unroll
        for (int u = 0; u < 4; u++) {
            int k = kb + ((u >> 1) << 3) + (u & 1);
            w[u] = (k < kbnd) ? W0[(size_t)k * N + n] : W1[(size_t)(k - kbnd) * N + n];
        }
        rr[2 * h] = packbf(w[0], w[1]);
        rr[2 * h + 1] = packbf(w[2], w[3]);
    }
    dst[idx] = make_uint4(rr[0], rr[1], rr[2], rr[3]);
}

__global__ void k_prepAttnT(const float* __restrict__ attn_w) {
    int idx = blockIdx.x * blockDim.x + threadIdx.x;
    if (idx < LL * 2 * DH) {
        int l = idx >> 11, k = idx & 2047;
        g_attnT[idx] = attn_w[(size_t)k * LL + l];
    }
}

// ---------------- A staging macro (per-lane fragment layout, bf16 pairs) ----------------
#define MMA_STAGE_A(KTS, NTHR)                                                 \
    for (int i = tid; i < (KTS) * 256; i += (NTHR)) {                          \
        int r = i & 3, ln = (i >> 2) & 31, mt = (i >> 7) & 1, kt = i >> 8;     \
        int gg_ = ln >> 2, tg_ = ln & 3;                                       \
        int row = mt * 16 + gg_ + ((r & 1) << 3);                              \
        int colG = c0 + kt * 16 + tg_ * 2 + ((r >> 1) << 3);                   \
        float2 v;                                                              \
        if (colG < bnd) {                                                      \
            const float* base = gather                                         \
                ? srcA0 + (size_t)toks[row] * bnd + colG                       \
                : srcA0 + (size_t)row * bnd + colG;                            \
            v = *reinterpret_cast<const float2*>(base);                        \
        } else {                                                               \
            v = *reinterpret_cast<const float2*>(                              \
                srcA1 + (size_t)row * DH + (colG - bnd));                      \
        }                                                                      \
        Af[i] = packbf(v.x, v.y);                                              \
    }

#define MMA_WRITE_PART(NTW, Co, N)                                             \
    {                                                                          \
        int gg_ = lane >> 2, tg_ = lane & 3;                                   \
        _Pragma("unroll")                                                      \
        for (int q = 0; q < (NTW); q++) {                                      \
            int ncol = (ntbase + q) * 8 + tg_ * 2;                             \
            _Pragma("unroll")                                                  \
            for (int mt = 0; mt < 2; mt++) {                                   \
                int row = mt * 16 + gg_;                                       \
                *reinterpret_cast<float2*>((Co) + (size_t)row * (N) + ncol) =  \
                    make_float2(acc[q][mt][0], acc[q][mt][1]);                 \
                *reinterpret_cast<float2*>((Co) + (size_t)(row + 8) * (N) + ncol) = \
                    make_float2(acc[q][mt][2], acc[q][mt][3]);                 \
            }                                                                  \
        }                                                                      \
    }

// consume one ktp (2 kt) from smem B for 4 n-tiles
#define MMA_CONSUME_KTP(ktpA, bidx)                                            \
    {                                                                          \
        uint4 A0 = *reinterpret_cast<const uint4*>(&Af[((ktpA) * 4 + 0) * 128 + lane * 4]); \
        uint4 A1 = *reinterpret_cast<const uint4*>(&Af[((ktpA) * 4 + 1) * 128 + lane * 4]); \
        uint4 A2 = *reinterpret_cast<const uint4*>(&Af[((ktpA) * 4 + 2) * 128 + lane * 4]); \
        uint4 A3 = *reinterpret_cast<const uint4*>(&Af[((ktpA) * 4 + 3) * 128 + lane * 4]); \
        _Pragma("unroll")                                                      \
        for (int q = 0; q < 4; q++) {                                          \
            uint4 b = Bs4[(bidx) + q * BSTRIDE + lane];                        \
            mma16816(acc[q][0], A0, make_uint2(b.x, b.y));                     \
            mma16816(acc[q][1], A1, make_uint2(b.x, b.y));                     \
            mma16816(acc[q][0], A2, make_uint2(b.z, b.w));                     \
            mma16816(acc[q][1], A3, make_uint2(b.z, b.w));                     \
        }                                                                      \
    }

// =========================================================================
// Gates GEMM + fused LSTM cell. grid = (16, S), 256 thr.
// Slice = 8 kt = 4 ktp (128 K). B staged fully in smem via cp.async (64KB).
// =========================================================================
__global__ void __launch_bounds__(256) k_gates_mma(
    const uint4* __restrict__ Bfrag4, int KTP_total,
    const float* __restrict__ srcA0, const float* __restrict__ srcA1, int bnd,
    int gather, const int* __restrict__ tokptr, int tokstride,
    const float* __restrict__ bias, int S, int t, int store_enc,
    int* __restrict__ cnt)
{
    extern __shared__ __align__(16) char dsm[];
    uint4* Bs4 = reinterpret_cast<uint4*>(dsm);              // 4096 uint4 = 64KB
    unsigned* Af = reinterpret_cast<unsigned*>(dsm + 65536); // 8KB
    __shared__ int toks[32];
    __shared__ int s_last;
    const int tid = threadIdx.x, lane = tid & 31, warp = tid >> 5;
    const int ktp0 = blockIdx.y * 4;
    const int c0 = ktp0 * 32;
    const int ntb = blockIdx.x * 32;

    // stage B (whole slice) via cp.async
    {
        unsigned sb = sptr(Bs4);
        const uint4* bbase = Bfrag4 + (size_t)ktp0 * 32;
        for (int i = tid; i < 4096; i += 256) {
            int nt_l = i >> 7, rem = i & 127;
            const uint4* src = bbase + (size_t)(ntb + nt_l) * KTP_total * 32 + rem;
            cpa16(sb + i * 16, src);
        }
        CP_COMMIT();
    }
    if (tid < 32) toks[tid] = gather ? tokptr[tid * tokstride] : 0;
    __syncthreads();
    MMA_STAGE_A(8, 256)
    CP_WAIT0();
    __syncthreads();

    const int ntbase = ntb + warp * 4;
    float acc[4][2][4];
#pragma unroll
    for (int q = 0; q < 4; q++)
#pragma unroll
        for (int mt = 0; mt < 2; mt++)
#pragma unroll
            for (int u = 0; u < 4; u++) acc[q][mt][u] = 0.f;

    const int BSTRIDE = 4 * 32;   // per-nt stride in uint4
#pragma unroll
    for (int ktp = 0; ktp < 4; ktp++) {
        MMA_CONSUME_KTP(ktp, (warp * 4) * BSTRIDE + ktp * 32)
    }

    float* Co = g_gp + (size_t)blockIdx.y * BB * G4;
    MMA_WRITE_PART(4, Co, G4)

    __threadfence();
    __syncthreads();
    if (tid == 0) s_last = atomicAdd(&cnt[t * 16 + blockIdx.x], 1);
    __syncthreads();
    if (s_last != S - 1) return;
    __threadfence();

    const int bx = blockIdx.x;
    for (int it = tid; it < 2048; it += 256) {
        int row = it >> 6, uu = it & 63;
        int P = 2 * bx + (uu >> 5), u = uu & 31;
        int base = (P << 7) + u;
        int d = (P << 5) + u;
        float ig = bias[d], fg = bias[d + DH], gg = bias[d + 2 * DH], og = bias[d + 3 * DH];
        for (int s = 0; s < S; s++) {
            const float* gp = g_gp + (size_t)s * BB * G4 + (size_t)row * G4 + base;
            ig += gp[0]; fg += gp[32]; gg += gp[64]; og += gp[96];
        }
        int hi_ = row * DH + d;
        float c = g_c[hi_];
        c = sigm(fg) * c + sigm(ig) * tanhf(gg);
        float h = sigm(og) * tanhf(c);
        g_c[hi_] = c;
        g_h[hi_] = h;
        if (store_enc) g_eo2[((size_t)row * LL + t) * DH + d] = h;
    }
}

// =========================================================================
// comb GEMM + fused bias/ReLU. grid = (4, 16), 256 thr. Same staging.
// =========================================================================
__global__ void __launch_bounds__(256) k_comb_mma(
    const uint4* __restrict__ Bfrag4, int KTP_total,
    const float* __restrict__ srcA0, const float* __restrict__ srcA1, int bnd,
    const int* __restrict__ tokptr,
    const float* __restrict__ bias, int t, int* __restrict__ cnt)
{
    extern __shared__ __align__(16) char dsm[];
    uint4* Bs4 = reinterpret_cast<uint4*>(dsm);
    unsigned* Af = reinterpret_cast<unsigned*>(dsm + 65536);
    __shared__ int toks[32];
    __shared__ int s_last;
    const int tid = threadIdx.x, lane = tid & 31, warp = tid >> 5;
    const int ktp0 = blockIdx.y * 4;
    const int c0 = ktp0 * 32;
    const int ntb = blockIdx.x * 32;
    const int gather = 1;

    {
        unsigned sb = sptr(Bs4);
        const uint4* bbase = Bfrag4 + (size_t)ktp0 * 32;
        for (int i = tid; i < 4096; i += 256) {
            int nt_l = i >> 7, rem = i & 127;
            const uint4* src = bbase + (size_t)(ntb + nt_l) * KTP_total * 32 + rem;
            cpa16(sb + i * 16, src);
        }
        CP_COMMIT();
    }
    if (tid < 32) toks[tid] = tokptr[tid];
    __syncthreads();
    MMA_STAGE_A(8, 256)
    CP_WAIT0();
    __syncthreads();

    const int ntbase = ntb + warp * 4;
    float acc[4][2][4];
#pragma unroll
    for (int q = 0; q < 4; q++)
#pragma unroll
        for (int mt = 0; mt < 2; mt++)
#pragma unroll
            for (int u = 0; u < 4; u++) acc[q][mt][u] = 0.f;

    const int BSTRIDE = 4 * 32;
#pragma unroll
    for (int ktp = 0; ktp < 4; ktp++) {
        MMA_CONSUME_KTP(ktp, (warp * 4) * BSTRIDE + ktp * 32)
    }

    float* Co = g_cpp + (size_t)blockIdx.y * BB * DH;
    MMA_WRITE_PART(4, Co, DH)

    __threadfence();
    __syncthreads();
    if (tid == 0) s_last = atomicAdd(&cnt[t * 4 + blockIdx.x], 1);
    __syncthreads();
    if (s_last != 15) return;
    __threadfence();

    for (int it = tid; it < 8192; it += 256) {
        int row = it >> 8, jj = it & 255;
        int j = blockIdx.x * 256 + jj;
        float s = bias[j];
#pragma unroll
        for (int u = 0; u < 16; u++)
            s += g_cpp[(size_t)u * BB * DH + (size_t)row * DH + j];
        g_inp[row * DH + j] = fmaxf(s, 0.f);
    }
}

// =========================================================================
// out projection: k-split 2, chunked double-buffered B (32KB x2),
// last-arrival fused finalize. grid = (125, 2), 256 thr.
// =========================================================================
__global__ void __launch_bounds__(256) k_outproj_mma(
    const uint4* __restrict__ Bfrag4,
    const float* __restrict__ out_b, float* __restrict__ out, int t,
    int* __restrict__ cnt)
{
    extern __shared__ __align__(16) char dsm[];
    uint4* Bs4 = reinterpret_cast<uint4*>(dsm);              // 2 x 2048 uint4 = 64KB
    unsigned* Af = reinterpret_cast<unsigned*>(dsm + 65536); // 32KB (reused as vals)
    __shared__ int s_last;
    const int tid = threadIdx.x, lane = tid & 31, warp = tid >> 5;
    const int KTP_total = 32;
    const int ktp0s = blockIdx.y * 16;     // 16 ktp per k-half
    const int c0 = blockIdx.y * 512;
    const int ntb = blockIdx.x * 32;
    unsigned sb = sptr(Bs4);

    // stage chunks 0 and 1
#pragma unroll
    for (int ch = 0; ch < 2; ch++) {
        const uint4* bbase = Bfrag4 + (size_t)(ktp0s + ch * 2) * 32;
        for (int i = tid; i < 2048; i += 256) {
            int nt_l = i >> 6, rem = i & 63;
            const uint4* src = bbase + (size_t)(ntb + nt_l) * KTP_total * 32 + rem;
            cpa16(sb + (ch * 2048 + i) * 16, src);
        }
        CP_COMMIT();
    }

    // stage A (32 kt) for this k-half
    for (int i = tid; i < 32 * 256; i += 256) {
        int r = i & 3, ln = (i >> 2) & 31, mt = (i >> 7) & 1, kt = i >> 8;
        int gg_ = ln >> 2, tg_ = ln & 3;
        int row = mt * 16 + gg_ + ((r & 1) << 3);
        int colG = c0 + kt * 16 + tg_ * 2 + ((r >> 1) << 3);
        float2 v = *reinterpret_cast<const float2*>(g_h + (size_t)row * DH + colG);
        Af[i] = packbf(v.x, v.y);
    }

    const int ntbase = ntb + warp * 4;
    float acc[4][2][4];
#pragma unroll
    for (int q = 0; q < 4; q++)
#pragma unroll
        for (int mt = 0; mt < 2; mt++)
#pragma unroll
            for (int u = 0; u < 4; u++) acc[q][mt][u] = 0.f;

    __syncthreads();   // A visible to all warps

    const int BSTRIDE = 2 * 32;   // per-nt stride within one buffer
#pragma unroll 1
    for (int ch = 0; ch < 8; ch++) {
        if (ch == 7) { CP_WAIT0(); } else { CP_WAIT1(); }
        __syncthreads();
        int bufb = (ch & 1) * 2048;
#pragma unroll
        for (int kl = 0; kl < 2; kl++) {
            MMA_CONSUME_KTP(ch * 2 + kl, bufb + (warp * 4) * BSTRIDE + kl * 32)
        }
        __syncthreads();
        if (ch + 2 < 8) {
            const uint4* bbase = Bfrag4 + (size_t)(ktp0s + (ch + 2) * 2) * 32;
            for (int i = tid; i < 2048; i += 256) {
                int nt_l = i >> 6, rem = i & 63;
                const uint4* src = bbase + (size_t)(ntb + nt_l) * KTP_total * 32 + rem;
                cpa16(sb + (bufb + i) * 16, src);
            }
            CP_COMMIT();
        }
    }

    // write my k-half partial
    float* Co = g_lg + (size_t)blockIdx.y * BB * VV;
    MMA_WRITE_PART(4, Co, VV)

    __threadfence();
    __syncthreads();
    if (tid == 0) s_last = atomicAdd(&cnt[t * NPO + blockIdx.x], 1);
    __syncthreads();
    if (s_last != 1) return;
    __threadfence();

    // finalize: vals = own acc + other half partial + bias; store raw logits
    const float* other = g_lg + (size_t)(1 - blockIdx.y) * BB * VV;
    float (*vals)[256] = reinterpret_cast<float (*)[256]>(Af);
    __syncthreads();
    {
        int gg_ = lane >> 2, tg_ = lane & 3;
#pragma unroll
        for (int q = 0; q < 4; q++) {
            int ncol = (ntbase + q) * 8 + tg_ * 2;
            int lcol = (warp * 4 + q) * 8 + tg_ * 2;
#pragma unroll
            for (int mt = 0; mt < 2; mt++) {
#pragma unroll
                for (int half = 0; half < 2; half++) {
                    int row = mt * 16 + gg_ + half * 8;
#pragma unroll
                    for (int cc = 0; cc < 2; cc++) {
                        float v = acc[q][mt][half * 2 + cc]
                                + other[(size_t)row * VV + ncol + cc]
                                + out_b[ncol + cc];
                        out[((size_t)row * LL + t) * VV + ncol + cc] = v;
                        vals[row][lcol + cc] = v;
                    }
                }
            }
        }
    }
    __syncthreads();

#pragma unroll
    for (int r4 = 0; r4 < 4; r4++) {
        int row = warp * 4 + r4;
        float s = 0.f, m = -1e30f;
        int mi = 0x7fffffff;
#pragma unroll
        for (int k = 0; k < 8; k++) {
            int c = lane + 32 * k;
            float v = vals[row][c];
            s += expf(v);
            if (v > m) { m = v; mi = blockIdx.x * 256 + c; }
        }
#pragma unroll
        for (int o = 16; o; o >>= 1) {
            s += __shfl_down_sync(0xffffffffu, s, o);
            float om = __shfl_down_sync(0xffffffffu, m, o);
            int   oi = __shfl_down_sync(0xffffffffu, mi, o);
            if (om > m || (om == m && oi < mi)) { m = om; mi = oi; }
        }
        if (lane == 0) {
            g_psum[row * NPO + blockIdx.x] = s;
            g_pmax[row * NPO + blockIdx.x] = m;
            g_pidx[row * NPO + blockIdx.x] = mi;
        }
    }
}

// =========================================================================
// Fused attention
// =========================================================================
__global__ void __launch_bounds__(256) k_attn(
    const float* __restrict__ dec_embed,
    const float* __restrict__ attn_b)
{
    __shared__ float cat_s[2 * DH];
    __shared__ float sp[4][LL];
    __shared__ float sc[LL], exs[LL], aw[LL];
    const int b = blockIdx.x, tid = threadIdx.x;
    const int tok = g_tok[b];

    for (int i = tid; i < DH; i += 256) {
        cat_s[i] = dec_embed[(size_t)tok * DH + i];
        cat_s[DH + i] = g_h[b * DH + i];
    }
    __syncthreads();
    {
        int l = tid & 63, kc = tid >> 6;
        int k0 = kc * 512;
        const float4* wp = reinterpret_cast<const float4*>(g_attnT + (size_t)l * 2048 + k0);
        const float4* cp = reinterpret_cast<const float4*>(cat_s + k0);
        float s = 0.f;
#pragma unroll 8
        for (int j = 0; j < 128; j++) {
            float4 w = wp[j];
            float4 c = cp[j];
            s += w.x * c.x + w.y * c.y + w.z * c.z + w.w * c.w;
        }
        sp[kc][l] = s;
    }
    __syncthreads();
    if (tid < LL)
        sc[tid] = attn_b[tid] + sp[0][tid] + sp[1][tid] + sp[2][tid] + sp[3][tid];
    __syncthreads();
    if (tid < LL) {
        float m = -1e30f;
        for (int i = 0; i < LL; i++) m = fmaxf(m, sc[i]);
        exs[tid] = expf(sc[tid] - m);
    }
    __syncthreads();
    if (tid < LL) {
        float tot = 0.f;
        for (int i = 0; i < LL; i++) tot += exs[i];
        aw[tid] = exs[tid] / tot;
    }
    __syncthreads();
    {
        int d0 = tid * 4;
        float4 a4 = make_float4(0.f, 0.f, 0.f, 0.f);
        const float4* ep = reinterpret_cast<const float4*>(g_eo2 + (size_t)b * LL * DH + d0);
#pragma unroll 8
        for (int l = 0; l < LL; l++) {
            float w = aw[l];
            float4 e = ep[(size_t)l * (DH / 4)];
            a4.x += w * e.x; a4.y += w * e.y; a4.z += w * e.z; a4.w += w * e.w;
        }
        *reinterpret_cast<float4*>(g_ctx + b * DH + d0) = a4;
    }
}

// ---------------- reduce 125 partials -> lse + token ----------------
__global__ void k_reduce(int t) {
    __shared__ float ss[128], sm[128];
    __shared__ int   si[128];
    int b = blockIdx.x, tid = threadIdx.x;
    float s = 0.f, m = -1e30f;
    int mi = 0x7fffffff;
    for (int i = tid; i < NPO; i += 128) {
        s += g_psum[b * NPO + i];
        float om = g_pmax[b * NPO + i];
        int oi = g_pidx[b * NPO + i];
        if (om > m || (om == m && oi < mi)) { m = om; mi = oi; }
    }
    ss[tid] = s; sm[tid] = m; si[tid] = mi;
    __syncthreads();
    for (int o = 64; o; o >>= 1) {
        if (tid < o) {
            ss[tid] += ss[tid + o];
            if (sm[tid + o] > sm[tid] ||
                (sm[tid + o] == sm[tid] && si[tid + o] < si[tid])) {
                sm[tid] = sm[tid + o];
                si[tid] = si[tid + o];
            }
        }
        __syncthreads();
    }
    if (tid == 0) {
        g_lse[t * BB + b] = logf(ss[0]);
        g_tok[b] = si[0];
    }
}

// ---------------- final pass: out -= lse ----------------
__global__ void k_finalize(float* __restrict__ out) {
    long idx = (long)blockIdx.x * blockDim.x + threadIdx.x;
    if (idx < (long)BB * LL * VV) {
        long r = idx / VV;
        int t = (int)(r % LL);
        int b = (int)(r / LL);
        out[idx] -= g_lse[t * BB + b];
    }
}

// ---------------- host orchestration ----------------
extern "C" void kernel_launch(void* const* d_in, const int* in_sizes, int n_in,
                              void* d_out, int out_size) {
    const int*   x         = (const int*)  d_in[0];
    const float* enc_embed = (const float*)d_in[1];
    const float* enc_wx    = (const float*)d_in[2];
    const float* enc_wh    = (const float*)d_in[3];
    const float* enc_b     = (const float*)d_in[4];
    const float* dec_embed = (const float*)d_in[5];
    const float* attn_w    = (const float*)d_in[6];
    const float* attn_b    = (const float*)d_in[7];
    const float* comb_w    = (const float*)d_in[8];
    const float* comb_b    = (const float*)d_in[9];
    const float* dec_wx    = (const float*)d_in[10];
    const float* dec_wh    = (const float*)d_in[11];
    const float* dec_b     = (const float*)d_in[12];
    const float* out_w     = (const float*)d_in[13];
    const float* out_b     = (const float*)d_in[14];
    float* out = (float*)d_out;

    uint4 *pBout, *pBdec, *pBenc, *pBcomb;
    float *p_h, *p_inp, *p_ctx;
    int *p_tok, *p_ce, *p_cd, *p_cc, *p_co;
    cudaGetSymbolAddress((void**)&pBout, Bout4);
    cudaGetSymbolAddress((void**)&pBdec, Bdec4);
    cudaGetSymbolAddress((void**)&pBenc, Benc4);
    cudaGetSymbolAddress((void**)&pBcomb, Bcomb4);
    cudaGetSymbolAddress((void**)&p_h, g_h);
    cudaGetSymbolAddress((void**)&p_inp, g_inp);
    cudaGetSymbolAddress((void**)&p_ctx, g_ctx);
    cudaGetSymbolAddress((void**)&p_tok, g_tok);
    cudaGetSymbolAddress((void**)&p_ce, g_cnt_enc);
    cudaGetSymbolAddress((void**)&p_cd, g_cnt_dec);
    cudaGetSymbolAddress((void**)&p_cc, g_cnt_comb);
    cudaGetSymbolAddress((void**)&p_co, g_cnt_out);

    cudaFuncSetAttribute(k_gates_mma, cudaFuncAttributeMaxDynamicSharedMemorySize, 73728);
    cudaFuncSetAttribute(k_comb_mma, cudaFuncAttributeMaxDynamicSharedMemorySize, 73728);
    cudaFuncSetAttribute(k_outproj_mma, cudaFuncAttributeMaxDynamicSharedMemorySize, 98304);

    // launches 1..3 before the hot gates class (ncu -s alignment)
    k_init<<<128, 256>>>(0);
    k_prepB4<<<3072, 256>>>(enc_wx, enc_wh, 512, G4, 48, 512, 1, pBenc);
    k_prepB4<<<1024, 256>>>(comb_w, comb_w, 2048, DH, 64, 128, 0, pBcomb);

    // ---------- encoder: 12 K-slices ----------
    for (int t = 0; t < LL; t++) {
        k_gates_mma<<<dim3(16, 12), 256, 73728>>>(pBenc, 48, enc_embed, p_h, 512,
                                                  1, x + t, LL, enc_b, 12, t, 1, p_ce);
    }

    k_prepB4<<<16000, 256>>>(out_w, out_w, 1024, VV, 32, 4000, 0, pBout);
    k_prepB4<<<4096, 256>>>(dec_wx, dec_wh, 1024, G4, 64, 512, 1, pBdec);
    k_prepAttnT<<<512, 256>>>(attn_w);

    // ---------- decoder ----------
    k_init<<<128, 256>>>(1);
    for (int t = 0; t < LL; t++) {
        k_attn<<<BB, 256>>>(dec_embed, attn_b);
        k_comb_mma<<<dim3(4, 16), 256, 73728>>>(pBcomb, 64, dec_embed, p_ctx, 1024,
                                                p_tok, comb_b, t, p_cc);
        k_gates_mma<<<dim3(16, 16), 256, 73728>>>(pBdec, 64, p_inp, p_h, 1024,
                                                  0, p_tok, 1, dec_b, 16, t, 0, p_cd);
        k_outproj_mma<<<dim3(NPO, 2), 256, 98304>>>(pBout, out_b, out, t, p_co);
        k_reduce<<<BB, 128>>>(t);
    }

    long total = (long)BB * LL * VV;
    k_finalize<<<(int)((total + 255) / 256), 256>>>(out);
}

// round 15
// speedup vs baseline: 1.1907x; 1.1907x over previous
#include <cuda_runtime.h>
#include <cuda_bf16.h>
#include <math.h>

#define BB 32
#define DH 1024
#define LL 64
#define VV 32000
#define G4 4096
#define NPO 125
#define GP 148          // persistent grid: <= SM count, single wave guaranteed

// ---- bf16 uint4 fragment weights [nt][ktp][lane] (2 kt per uint4) ----
__device__ uint4 Bout4[(size_t)4000 * 32 * 32];
__device__ uint4 Bdec4[(size_t)512 * 64 * 32];   // gate-permuted
__device__ uint4 Benc4[(size_t)512 * 48 * 32];   // gate-permuted
__device__ uint4 Bcomb4[(size_t)128 * 64 * 32];
__device__ float g_attnT[LL * 2 * DH];

// ---- state ----
__device__ float g_h[BB * DH];
__device__ float g_c[BB * DH];
__device__ float g_inp[BB * DH];
__device__ float g_ctx[BB * DH];
__device__ float g_eo2[BB * LL * DH];
__device__ float g_gp[16 * BB * G4];
__device__ float g_cpp[16 * BB * DH];
__device__ float g_psum[BB * NPO];
__device__ float g_pmax[BB * NPO];
__device__ int   g_pidx[BB * NPO];
__device__ int   g_tok[BB];
__device__ float g_lse[LL * BB];
__device__ int g_cnt_enc[LL * 16];
__device__ int g_cnt_dec[LL * 16];
__device__ int g_cnt_comb[LL * 4];
__device__ int g_cnt2[LL];
__device__ int g_barc;
__device__ volatile int g_bars;

// ---- helpers ----
__device__ __forceinline__ unsigned packbf(float x, float y) {
    unsigned lo = __bfloat16_as_ushort(__float2bfloat16_rn(x));
    unsigned hi = __bfloat16_as_ushort(__float2bfloat16_rn(y));
    return lo | (hi << 16);
}
__device__ __forceinline__ void mma16816(float* c, uint4 a, uint2 b) {
    asm volatile(
        "mma.sync.aligned.m16n8k16.row.col.f32.bf16.bf16.f32 "
        "{%0,%1,%2,%3}, {%4,%5,%6,%7}, {%8,%9}, {%0,%1,%2,%3};"
        : "+f"(c[0]), "+f"(c[1]), "+f"(c[2]), "+f"(c[3])
        : "r"(a.x), "r"(a.y), "r"(a.z), "r"(a.w), "r"(b.x), "r"(b.y));
}
__device__ __forceinline__ float sigm(float x) { return 1.f / (1.f + expf(-x)); }
__device__ __forceinline__ unsigned sptr(const void* p) {
    return (unsigned)__cvta_generic_to_shared(p);
}
__device__ __forceinline__ void cpa16(unsigned s, const void* g) {
    asm volatile("cp.async.cg.shared.global [%0], [%1], 16;" :: "r"(s), "l"(g));
}
#define CP_COMMIT() asm volatile("cp.async.commit_group;")
#define CP_WAIT0()  asm volatile("cp.async.wait_group 0;")
#define CP_WAIT1()  asm volatile("cp.async.wait_group 1;")

// grid-wide sense-reversing barrier; GP<=148 => all blocks in wave 1, no deadlock
__device__ __forceinline__ void gsync() {
    __syncthreads();
    if (threadIdx.x == 0) {
        __threadfence();
        int s = g_bars;
        if (atomicAdd(&g_barc, 1) == GP - 1) {
            g_barc = 0;
            __threadfence();
            g_bars = s ^ 1;
        } else {
            while (g_bars == s) __nanosleep(64);
        }
        __threadfence();
    }
    __syncthreads();
}

#define MMA_STAGE_A(KTS, NTHR)                                                 \
    for (int i = tid; i < (KTS) * 256; i += (NTHR)) {                          \
        int r = i & 3, ln = (i >> 2) & 31, mt = (i >> 7) & 1, kt = i >> 8;     \
        int gg_ = ln >> 2, tg_ = ln & 3;                                       \
        int row = mt * 16 + gg_ + ((r & 1) << 3);                              \
        int colG = c0 + kt * 16 + tg_ * 2 + ((r >> 1) << 3);                   \
        float2 v;                                                              \
        if (colG < bnd) {                                                      \
            const float* base = gather                                         \
                ? srcA0 + (size_t)toks[row] * bnd + colG                       \
                : srcA0 + (size_t)row * bnd + colG;                            \
            v = *reinterpret_cast<const float2*>(base);                        \
        } else {                                                               \
            v = *reinterpret_cast<const float2*>(                              \
                srcA1 + (size_t)row * DH + (colG - bnd));                      \
        }                                                                      \
        Af[i] = packbf(v.x, v.y);                                              \
    }

#define MMA_WRITE_PART(NTW, Co, N)                                             \
    {                                                                          \
        int gg_ = lane >> 2, tg_ = lane & 3;                                   \
        _Pragma("unroll")                                                      \
        for (int q = 0; q < (NTW); q++) {                                      \
            int ncol = (ntbase + q) * 8 + tg_ * 2;                             \
            _Pragma("unroll")                                                  \
            for (int mt = 0; mt < 2; mt++) {                                   \
                int row = mt * 16 + gg_;                                       \
                *reinterpret_cast<float2*>((Co) + (size_t)row * (N) + ncol) =  \
                    make_float2(acc[q][mt][0], acc[q][mt][1]);                 \
                *reinterpret_cast<float2*>((Co) + (size_t)(row + 8) * (N) + ncol) = \
                    make_float2(acc[q][mt][2], acc[q][mt][3]);                 \
            }                                                                  \
        }                                                                      \
    }

#define MMA_CONSUME_KTP(ktpA, bidx)                                            \
    {                                                                          \
        uint4 A0 = *reinterpret_cast<const uint4*>(&Af[((ktpA) * 4 + 0) * 128 + lane * 4]); \
        uint4 A1 = *reinterpret_cast<const uint4*>(&Af[((ktpA) * 4 + 1) * 128 + lane * 4]); \
        uint4 A2 = *reinterpret_cast<const uint4*>(&Af[((ktpA) * 4 + 2) * 128 + lane * 4]); \
        uint4 A3 = *reinterpret_cast<const uint4*>(&Af[((ktpA) * 4 + 3) * 128 + lane * 4]); \
        _Pragma("unroll")                                                      \
        for (int q = 0; q < 4; q++) {                                          \
            uint4 b = Bs4[(bidx) + q * BSTRIDE + lane];                        \
            mma16816(acc[q][0], A0, make_uint2(b.x, b.y));                     \
            mma16816(acc[q][1], A1, make_uint2(b.x, b.y));                     \
            mma16816(acc[q][0], A2, make_uint2(b.z, b.w));                     \
            mma16816(acc[q][1], A3, make_uint2(b.z, b.w));                     \
        }                                                                      \
    }

// ---- gates GEMM + last-arrival LSTM cell (enc: S=6, dec: S=8) ----
__device__ void gates_body(char* dsm, const uint4* Bf, int KTPT, int ktp0base,
                           int nchunks, const float* srcA0, const float* srcA1,
                           int bnd, int gather, const int* tokptr, int tokstride,
                           const float* bias, int S, int t, int store_enc,
                           int* cnt, int bx, int ks, int* toks, int* s_last) {
    uint4* Bs4 = reinterpret_cast<uint4*>(dsm);
    unsigned* Af = reinterpret_cast<unsigned*>(dsm + 65536);
    const int tid = threadIdx.x, lane = tid & 31, warp = tid >> 5;
    const int ntb = bx * 32;
    if (tid < 32) toks[tid] = gather ? tokptr[tid * tokstride] : 0;
    float acc[4][2][4];
#pragma unroll
    for (int q = 0; q < 4; q++)
#pragma unroll
        for (int mt = 0; mt < 2; mt++)
#pragma unroll
            for (int u = 0; u < 4; u++) acc[q][mt][u] = 0.f;
    const int BSTRIDE = 128;
#pragma unroll 1
    for (int c = 0; c < nchunks; c++) {
        const int ktp0 = ktp0base + c * 4, c0 = ktp0 * 32;
        unsigned sb = sptr(Bs4);
        for (int i = tid; i < 4096; i += 256) {
            int ntl = i >> 7, rem = i & 127;
            cpa16(sb + i * 16, Bf + ((size_t)(ntb + ntl) * KTPT + ktp0) * 32 + rem);
        }
        CP_COMMIT();
        __syncthreads();
        MMA_STAGE_A(8, 256)
        CP_WAIT0();
        __syncthreads();
#pragma unroll
        for (int kp = 0; kp < 4; kp++) {
            MMA_CONSUME_KTP(kp, (warp * 4) * BSTRIDE + kp * 32)
        }
        __syncthreads();
    }
    const int ntbase = ntb + warp * 4;
    float* Co = g_gp + (size_t)ks * BB * G4;
    MMA_WRITE_PART(4, Co, G4)
    __threadfence();
    __syncthreads();
    if (tid == 0) *s_last = atomicAdd(&cnt[t * 16 + bx], 1);
    __syncthreads();
    if (*s_last == S - 1) {
        __threadfence();
        for (int it = tid; it < 2048; it += 256) {
            int row = it >> 6, uu = it & 63;
            int P = 2 * bx + (uu >> 5), u = uu & 31;
            int base = (P << 7) + u;
            int d = (P << 5) + u;
            float ig = bias[d], fg = bias[d + DH], gg = bias[d + 2 * DH], og = bias[d + 3 * DH];
            for (int s = 0; s < S; s++) {
                const float* gp = g_gp + (size_t)s * BB * G4 + (size_t)row * G4 + base;
                ig += gp[0]; fg += gp[32]; gg += gp[64]; og += gp[96];
            }
            int hi_ = row * DH + d;
            float cc = g_c[hi_];
            cc = sigm(fg) * cc + sigm(ig) * tanhf(gg);
            float h = sigm(og) * tanhf(cc);
            g_c[hi_] = cc;
            g_h[hi_] = h;
            if (store_enc) g_eo2[((size_t)row * LL + t) * DH + d] = h;
        }
    }
}

// ---- comb GEMM + last-arrival bias/ReLU (64 blocks: 4 bx x 16 ks) ----
__device__ void comb_body(char* dsm, const float* dec_embed, const float* comb_b,
                          int t, int bx, int ks, int* toks, int* s_last) {
    uint4* Bs4 = reinterpret_cast<uint4*>(dsm);
    unsigned* Af = reinterpret_cast<unsigned*>(dsm + 65536);
    const int tid = threadIdx.x, lane = tid & 31, warp = tid >> 5;
    const int ntb = bx * 32;
    const int ktp0 = ks * 4, c0 = ktp0 * 32;
    const int bnd = DH, gather = 1;
    const float* srcA0 = dec_embed;
    const float* srcA1 = g_ctx;
    if (tid < 32) toks[tid] = g_tok[tid];
    {
        unsigned sb = sptr(Bs4);
        for (int i = tid; i < 4096; i += 256) {
            int ntl = i >> 7, rem = i & 127;
            cpa16(sb + i * 16, Bcomb4 + ((size_t)(ntb + ntl) * 64 + ktp0) * 32 + rem);
        }
        CP_COMMIT();
    }
    __syncthreads();
    MMA_STAGE_A(8, 256)
    CP_WAIT0();
    __syncthreads();
    const int ntbase = ntb + warp * 4;
    float acc[4][2][4];
#pragma unroll
    for (int q = 0; q < 4; q++)
#pragma unroll
        for (int mt = 0; mt < 2; mt++)
#pragma unroll
            for (int u = 0; u < 4; u++) acc[q][mt][u] = 0.f;
    const int BSTRIDE = 128;
#pragma unroll
    for (int kp = 0; kp < 4; kp++) {
        MMA_CONSUME_KTP(kp, (warp * 4) * BSTRIDE + kp * 32)
    }
    float* Co = g_cpp + (size_t)ks * BB * DH;
    MMA_WRITE_PART(4, Co, DH)
    __threadfence();
    __syncthreads();
    if (tid == 0) *s_last = atomicAdd(&g_cnt_comb[t * 4 + bx], 1);
    __syncthreads();
    if (*s_last == 15) {
        __threadfence();
        for (int it = tid; it < 8192; it += 256) {
            int row = it >> 8, jj = it & 255;
            int j = bx * 256 + jj;
            float s = comb_b[j];
#pragma unroll
            for (int u = 0; u < 16; u++)
                s += g_cpp[(size_t)u * BB * DH + (size_t)row * DH + j];
            g_inp[row * DH + j] = fmaxf(s, 0.f);
        }
    }
}

// ---- attention (1 block per batch row) ----
__device__ void attn_body(char* dsm, const float* dec_embed,
                          const float* attn_b, int b) {
    float* cat_s = reinterpret_cast<float*>(dsm);
    float* sp = cat_s + 2048;
    float* sc = sp + 256;
    float* exs = sc + 64;
    float* aw = exs + 64;
    const int tid = threadIdx.x;
    const int tok = g_tok[b];
    for (int i = tid; i < DH; i += 256) {
        cat_s[i] = dec_embed[(size_t)tok * DH + i];
        cat_s[DH + i] = g_h[b * DH + i];
    }
    __syncthreads();
    {
        int l = tid & 63, kc = tid >> 6;
        int k0 = kc * 512;
        const float4* wp = reinterpret_cast<const float4*>(g_attnT + (size_t)l * 2048 + k0);
        const float4* cp = reinterpret_cast<const float4*>(cat_s + k0);
        float s = 0.f;
#pragma unroll 8
        for (int j = 0; j < 128; j++) {
            float4 w = wp[j], c = cp[j];
            s += w.x * c.x + w.y * c.y + w.z * c.z + w.w * c.w;
        }
        sp[kc * 64 + l] = s;
    }
    __syncthreads();
    if (tid < 64)
        sc[tid] = attn_b[tid] + sp[tid] + sp[64 + tid] + sp[128 + tid] + sp[192 + tid];
    __syncthreads();
    if (tid < 64) {
        float m = -1e30f;
        for (int i = 0; i < 64; i++) m = fmaxf(m, sc[i]);
        exs[tid] = expf(sc[tid] - m);
    }
    __syncthreads();
    if (tid < 64) {
        float tot = 0.f;
        for (int i = 0; i < 64; i++) tot += exs[i];
        aw[tid] = exs[tid] / tot;
    }
    __syncthreads();
    {
        int d0 = tid * 4;
        float4 a4 = make_float4(0.f, 0.f, 0.f, 0.f);
        const float4* ep = reinterpret_cast<const float4*>(g_eo2 + (size_t)b * LL * DH + d0);
#pragma unroll 8
        for (int l = 0; l < 64; l++) {
            float w = aw[l];
            float4 e = ep[(size_t)l * (DH / 4)];
            a4.x += w * e.x; a4.y += w * e.y; a4.z += w * e.z; a4.w += w * e.w;
        }
        *reinterpret_cast<float4*>(g_ctx + b * DH + d0) = a4;
    }
}

// ---- out projection: 125 blocks, FULL K=1024 (two A-halves), fused finalize ----
__device__ void outproj_body(char* dsm, const float* out_b, float* out, int t,
                             int bxO, int* s_last) {
    uint4* Bs4 = reinterpret_cast<uint4*>(dsm);              // 2 x 2048 uint4 = 64KB
    unsigned* Af = reinterpret_cast<unsigned*>(dsm + 65536); // 32KB (later vals)
    const int tid = threadIdx.x, lane = tid & 31, warp = tid >> 5;
    const int ntb = bxO * 32;
    unsigned sb = sptr(Bs4);
    const int BSTRIDE = 64;
    float acc[4][2][4];
#pragma unroll
    for (int q = 0; q < 4; q++)
#pragma unroll
        for (int mt = 0; mt < 2; mt++)
#pragma unroll
            for (int u = 0; u < 4; u++) acc[q][mt][u] = 0.f;

#pragma unroll 1
    for (int kh = 0; kh < 2; kh++) {
        const int c0 = kh * 512;
        const int ktp0s = kh * 16;
        __syncthreads();
        // stage A half (32 kt)
        for (int i = tid; i < 8192; i += 256) {
            int r = i & 3, ln = (i >> 2) & 31, mt = (i >> 7) & 1, kt = i >> 8;
            int row = mt * 16 + (ln >> 2) + ((r & 1) << 3);
            int colG = c0 + kt * 16 + (ln & 3) * 2 + ((r >> 1) << 3);
            float2 v = *reinterpret_cast<const float2*>(g_h + (size_t)row * DH + colG);
            Af[i] = packbf(v.x, v.y);
        }
        // prime B chunks 0,1
#pragma unroll
        for (int ch = 0; ch < 2; ch++) {
            for (int i = tid; i < 2048; i += 256) {
                int ntl = i >> 6, rem = i & 63;
                cpa16(sb + (ch * 2048 + i) * 16,
                      Bout4 + ((size_t)(ntb + ntl) * 32 + ktp0s + ch * 2) * 32 + rem);
            }
            CP_COMMIT();
        }
#pragma unroll 1
        for (int ch = 0; ch < 8; ch++) {
            if (ch == 7) { CP_WAIT0(); } else { CP_WAIT1(); }
            __syncthreads();
            int bufb = (ch & 1) * 2048;
#pragma unroll
            for (int kl = 0; kl < 2; kl++) {
                MMA_CONSUME_KTP(ch * 2 + kl, bufb + (warp * 4) * BSTRIDE + kl * 32)
            }
            __syncthreads();
            if (ch + 2 < 8) {
                for (int i = tid; i < 2048; i += 256) {
                    int ntl = i >> 6, rem = i & 63;
                    cpa16(sb + (bufb + i) * 16,
                          Bout4 + ((size_t)(ntb + ntl) * 32 + ktp0s + (ch + 2) * 2) * 32 + rem);
                }
                CP_COMMIT();
            }
        }
    }

    // epilogue: bias + store raw logits + stage vals
    const int ntbase = ntb + warp * 4;
    __syncthreads();
    float (*vals)[256] = reinterpret_cast<float (*)[256]>(Af);
    {
        int gg_ = lane >> 2, tg_ = lane & 3;
#pragma unroll
        for (int q = 0; q < 4; q++) {
            int ncol = (ntbase + q) * 8 + tg_ * 2;
            int lcol = (warp * 4 + q) * 8 + tg_ * 2;
#pragma unroll
            for (int mt = 0; mt < 2; mt++) {
#pragma unroll
                for (int half = 0; half < 2; half++) {
                    int row = mt * 16 + gg_ + half * 8;
#pragma unroll
                    for (int cc = 0; cc < 2; cc++) {
                        float v = acc[q][mt][half * 2 + cc] + out_b[ncol + cc];
                        out[((size_t)row * LL + t) * VV + ncol + cc] = v;
                        vals[row][lcol + cc] = v;
                    }
                }
            }
        }
    }
    __syncthreads();
    // per-row partial lse / argmax over this block's 256 cols
#pragma unroll
    for (int r4 = 0; r4 < 4; r4++) {
        int row = warp * 4 + r4;
        float s = 0.f, m = -1e30f;
        int mi = 0x7fffffff;
#pragma unroll
        for (int k = 0; k < 8; k++) {
            int c = lane + 32 * k;
            float v = vals[row][c];
            s += expf(v);
            if (v > m) { m = v; mi = bxO * 256 + c; }
        }
#pragma unroll
        for (int o = 16; o; o >>= 1) {
            s += __shfl_down_sync(0xffffffffu, s, o);
            float om = __shfl_down_sync(0xffffffffu, m, o);
            int   oi = __shfl_down_sync(0xffffffffu, mi, o);
            if (om > m || (om == m && oi < mi)) { m = om; mi = oi; }
        }
        if (lane == 0) {
            g_psum[row * NPO + bxO] = s;
            g_pmax[row * NPO + bxO] = m;
            g_pidx[row * NPO + bxO] = mi;
        }
    }
    __threadfence();
    __syncthreads();
    if (tid == 0) *s_last = atomicAdd(&g_cnt2[t], 1);
    __syncthreads();
    if (*s_last == NPO - 1) {
        __threadfence();
        int b = tid >> 3, j8 = tid & 7;
        float s = 0.f, m = -1e30f;
        int mi = 0x7fffffff;
        for (int i = j8; i < NPO; i += 8) {
            s += g_psum[b * NPO + i];
            float om = g_pmax[b * NPO + i];
            int oi = g_pidx[b * NPO + i];
            if (om > m || (om == m && oi < mi)) { m = om; mi = oi; }
        }
#pragma unroll
        for (int o = 4; o; o >>= 1) {
            s += __shfl_down_sync(0xffffffffu, s, o, 8);
            float om = __shfl_down_sync(0xffffffffu, m, o, 8);
            int   oi = __shfl_down_sync(0xffffffffu, mi, o, 8);
            if (om > m || (om == m && oi < mi)) { m = om; mi = oi; }
        }
        if (j8 == 0) {
            g_lse[t * BB + b] = logf(s);
            g_tok[b] = mi;
        }
    }
}

// =========================================================================
// Persistent kernel: grid GP=148 (one wave, co-residency guaranteed)
// =========================================================================
__global__ void __launch_bounds__(256) k_persist(
    const int* __restrict__ x, const float* __restrict__ enc_embed,
    const float* __restrict__ enc_b, const float* __restrict__ dec_embed,
    const float* __restrict__ attn_b, const float* __restrict__ comb_b,
    const float* __restrict__ dec_b, const float* __restrict__ out_b,
    float* __restrict__ out)
{
    extern __shared__ __align__(16) char dsm[];
    __shared__ int s_toks[32];
    __shared__ int s_last;
    const int blk = blockIdx.x, tid = threadIdx.x;
    const int gt = blk * 256 + tid;

    // per-replay init
    for (int i = gt; i < BB * DH; i += GP * 256) { g_h[i] = 0.f; g_c[i] = 0.f; }
    for (int i = gt; i < LL * 16; i += GP * 256) { g_cnt_enc[i] = 0; g_cnt_dec[i] = 0; }
    for (int i = gt; i < LL * 4; i += GP * 256) g_cnt_comb[i] = 0;
    for (int i = gt; i < LL; i += GP * 256) g_cnt2[i] = 0;
    gsync();

    // ---------- encoder: 96 logical blocks (16 bx x 6 ks of 256 K) ----------
    for (int t = 0; t < LL; t++) {
        if (blk < 96)
            gates_body(dsm, Benc4, 48, (blk >> 4) * 8, 2, enc_embed, g_h, 512, 1,
                       x + t, LL, enc_b, 6, t, 1, g_cnt_enc, blk & 15, blk >> 4,
                       s_toks, &s_last);
        gsync();
    }

    // decoder re-init
    for (int i = gt; i < BB * DH; i += GP * 256) { g_h[i] = 0.f; g_c[i] = 0.f; }
    if (blk == 0 && tid < BB) g_tok[tid] = 127;
    gsync();

    // ---------- decoder: 4 phases/step ----------
    for (int t = 0; t < LL; t++) {
        if (blk < 32) attn_body(dsm, dec_embed, attn_b, blk);
        gsync();
        if (blk < 64) comb_body(dsm, dec_embed, comb_b, t, blk & 3, blk >> 2,
                                s_toks, &s_last);
        gsync();
        if (blk < 128)
            gates_body(dsm, Bdec4, 64, (blk >> 4) * 8, 2, g_inp, g_h, 1024, 0,
                       g_tok, 1, dec_b, 8, t, 0, g_cnt_dec, blk & 15, blk >> 4,
                       s_toks, &s_last);
        gsync();
        if (blk < NPO) outproj_body(dsm, out_b, out, t, blk, &s_last);
        gsync();
    }
}

// ---- prep kernels ----
__global__ void k_prepB4(const float* __restrict__ W0, const float* __restrict__ W1,
                         int kbnd, int N, int KTPT, int NT, int perm,
                         uint4* __restrict__ dst) {
    size_t idx = (size_t)blockIdx.x * blockDim.x + threadIdx.x;
    size_t total = (size_t)NT * KTPT * 32;
    if (idx >= total) return;
    int lane = (int)(idx & 31);
    int ktp = (int)((idx >> 5) % KTPT);
    int nt = (int)(idx / ((size_t)KTPT * 32));
    int g = lane >> 2, tg = lane & 3;
    int n = nt * 8 + g;
    if (perm) {
        int p = n >> 7, r = n & 127, gate = r >> 5, u = r & 31;
        n = gate * DH + (p << 5) + u;
    }
    unsigned rr[4];
#pragma unroll
    for (int h = 0; h < 2; h++) {
        int kt = 2 * ktp + h;
        int kb = kt * 16 + tg * 2;
        float w[4];
#pragma unroll
        for (int u = 0; u < 4; u++) {
            int k = kb + ((u >> 1) << 3) + (u & 1);
            w[u] = (k < kbnd) ? W0[(size_t)k * N + n] : W1[(size_t)(k - kbnd) * N + n];
        }
        rr[2 * h] = packbf(w[0], w[1]);
        rr[2 * h + 1] = packbf(w[2], w[3]);
    }
    dst[idx] = make_uint4(rr[0], rr[1], rr[2], rr[3]);
}

__global__ void k_prepAttnT(const float* __restrict__ attn_w) {
    int idx = blockIdx.x * blockDim.x + threadIdx.x;
    if (idx < LL * 2 * DH) {
        int l = idx >> 11, k = idx & 2047;
        g_attnT[idx] = attn_w[(size_t)k * LL + l];
    }
}

__global__ void k_finalize(float* __restrict__ out) {
    long idx = (long)blockIdx.x * blockDim.x + threadIdx.x;
    if (idx < (long)BB * LL * VV) {
        long r = idx / VV;
        int t = (int)(r % LL);
        int b = (int)(r / LL);
        out[idx] -= g_lse[t * BB + b];
    }
}

// ---- host ----
extern "C" void kernel_launch(void* const* d_in, const int* in_sizes, int n_in,
                              void* d_out, int out_size) {
    const int*   x         = (const int*)  d_in[0];
    const float* enc_embed = (const float*)d_in[1];
    const float* enc_wx    = (const float*)d_in[2];
    const float* enc_wh    = (const float*)d_in[3];
    const float* enc_b     = (const float*)d_in[4];
    const float* dec_embed = (const float*)d_in[5];
    const float* attn_w    = (const float*)d_in[6];
    const float* attn_b    = (const float*)d_in[7];
    const float* comb_w    = (const float*)d_in[8];
    const float* comb_b    = (const float*)d_in[9];
    const float* dec_wx    = (const float*)d_in[10];
    const float* dec_wh    = (const float*)d_in[11];
    const float* dec_b     = (const float*)d_in[12];
    const float* out_w     = (const float*)d_in[13];
    const float* out_b     = (const float*)d_in[14];
    float* out = (float*)d_out;

    uint4 *pBout, *pBdec, *pBenc, *pBcomb;
    cudaGetSymbolAddress((void**)&pBout, Bout4);
    cudaGetSymbolAddress((void**)&pBdec, Bdec4);
    cudaGetSymbolAddress((void**)&pBenc, Benc4);
    cudaGetSymbolAddress((void**)&pBcomb, Bcomb4);

    cudaFuncSetAttribute(k_persist, cudaFuncAttributeMaxDynamicSharedMemorySize, 98304);

    k_prepB4<<<3072, 256>>>(enc_wx, enc_wh, 512, G4, 48, 512, 1, pBenc);
    k_prepB4<<<1024, 256>>>(comb_w, comb_w, 2048, DH, 64, 128, 0, pBcomb);
    k_prepB4<<<16000, 256>>>(out_w, out_w, 1024, VV, 32, 4000, 0, pBout);
    k_prepB4<<<4096, 256>>>(dec_wx, dec_wh, 1024, G4, 64, 512, 1, pBdec);
    k_prepAttnT<<<512, 256>>>(attn_w);

    k_persist<<<GP, 256, 98304>>>(x, enc_embed, enc_b, dec_embed, attn_b,
                                  comb_b, dec_b, out_b, out);

    long total = (long)BB * LL * VV;
    k_finalize<<<(int)((total + 255) / 256), 256>>>(out);
}